// round 8
// baseline (speedup 1.0000x reference)
#include <cuda_runtime.h>
#include <cuda_fp16.h>
#include <cstdint>

#define BN   2
#define NN   128
#define NP   (NN*NN)          // 16384
#define TOT  (BN*NP)          // 32768
#define KC   131
#define CC   21
#define WW   49
#define NPAIR 66              // 65 real channel pairs + 1 phantom-padded

// stage1 tile: 16x8 outputs, 256 threads (2 lanes/pixel), halo 22x14
#define S1W   16
#define S1H   8
#define S1HW  22
#define S1HH  14
#define S1PX  (S1HW*S1HH)     // 308
#define S1STR 24              // halo row stride in uint2 (8B) units
#define S1ZROW (S1STR*S1HH)   // 336: zero-row base
#define S1BUF  (S1ZROW+S1STR) // 360 uint2 per buffer

// stage2 tile
#define T2W  16
#define T2H  8
#define HW2  22
#define HPX  (HW2*14)         // 308
#define CPAD 28

// ---- scratch (static device globals; no runtime allocation) ----
__device__ float g_A[(size_t)WW*TOT];              // ~6.4MB

__device__ __forceinline__ unsigned h2u(__half2 v) { return *reinterpret_cast<unsigned*>(&v); }
__device__ __forceinline__ __half2 u2h(unsigned v) { return *reinterpret_cast<__half2*>(&v); }

// ---------------------------------------------------------------
// stage 1: channel-paired, lane-split window softmax accumulate.
//   smem per pixel: uint2 = (half2(E_k,E_k1), half2(R_k,R_k1))
//   per tap: LDS.64 + 2 HMUL2 + HMAX2 + HADD2 (+ HFMA2 epilogue)
//   even lane: window rows 0..3 (w 0..27); odd lane: zero-dummy +
//   rows 4..6 (w 28..48). esum joined with one shfl_xor.
//   Ah accumulated in half2, flushed to float every 8 pairs.
// ---------------------------------------------------------------
__global__ void __launch_bounds__(256, 2)
stage1_kernel(const float* __restrict__ integ,
              const int*   __restrict__ mask,
              const float* __restrict__ cp) {
    __shared__ uint2 sh[2][S1BUF];
    __shared__ float scp[KC + 1];

    int t = threadIdx.x;
    if (t < KC) scp[t] = cp[t];
    if (t == 0) scp[KC] = 0.0f;                  // phantom channel weight
    if (t < S1STR) {                             // zero rows (both buffers)
        sh[0][S1ZROW + t] = make_uint2(0u, 0u);
        sh[1][S1ZROW + t] = make_uint2(0u, 0u);
    }

    int b  = blockIdx.z;
    int x0 = blockIdx.x * S1W;
    int y0 = blockIdx.y * S1H;

    int h   = t & 1;                             // w-half
    int pix = t >> 1;                            // 0..127
    int tx  = pix & 15, ty = pix >> 4;

    const float* __restrict__ inb = integ + (size_t)b * KC * NP;
    const int*   __restrict__ mkb = mask  + (size_t)b * NP;

    // halo fill slots: slot0 = t (<308 always), slot1 = t+256 (first 52 threads)
    int  si0, si1 = S1ZROW, off0 = 0, off1 = 0;
    bool ok0 = false, ok1 = false, has1;
    float m0 = 0.f, m1 = 0.f;
    {
        int s0 = t, s1 = t + 256;
        has1 = (s1 < S1PX);
        int hy0 = s0 / S1HW, hx0 = s0 - hy0 * S1HW;
        si0 = hy0 * S1STR + hx0;
        int gy0 = y0 + hy0 - 3, gx0 = x0 + hx0 - 3;
        ok0 = ((unsigned)gy0 < NN) && ((unsigned)gx0 < NN);
        if (ok0) { off0 = gy0 * NN + gx0; m0 = (float)mkb[off0]; }
        if (has1) {
            int hy1 = s1 / S1HW, hx1 = s1 - hy1 * S1HW;
            si1 = hy1 * S1STR + hx1;
            int gy1 = y0 + hy1 - 3, gx1 = x0 + hx1 - 3;
            ok1 = ((unsigned)gy1 < NN) && ((unsigned)gx1 < NN);
            if (ok1) { off1 = gy1 * NN + gx1; m1 = (float)mkb[off1]; }
        }
    }

    // row base offsets (uint2 index) per lane
    int c00 = ty * S1STR + tx;
    int rbo[4];
    if (h == 0) {
        rbo[0] = c00;             rbo[1] = c00 + S1STR;
        rbo[2] = c00 + 2 * S1STR; rbo[3] = c00 + 3 * S1STR;
    } else {
        rbo[0] = S1ZROW;          rbo[1] = c00 + 4 * S1STR;
        rbo[2] = c00 + 5 * S1STR; rbo[3] = c00 + 6 * S1STR;
    }

    float   A[28];
    __half2 Ah[28];
    #pragma unroll
    for (int j = 0; j < 28; j++) { A[j] = 0.0f; Ah[j] = u2h(0u); }

    // prefetch + exp for pair 0
    float fa0, fb0, fa1, fb1;
    fa0 = ok0 ? __ldg(inb + off0) : 0.f;
    fb0 = ok0 ? __ldg(inb + NP + off0) : 0.f;
    fa1 = (has1 && ok1) ? __ldg(inb + off1) : 0.f;
    fb1 = (has1 && ok1) ? __ldg(inb + NP + off1) : 0.f;

    uint2 v0, v1;
    {
        float va = fa0 * m0, vb = fb0 * m0;
        v0 = ok0 ? make_uint2(h2u(__floats2half2_rn(__expf(va), __expf(vb))),
                              h2u(__floats2half2_rn(__expf(-va), __expf(-vb))))
                 : make_uint2(0u, 0u);
        float vc = fa1 * m1, vd = fb1 * m1;
        v1 = ok1 ? make_uint2(h2u(__floats2half2_rn(__expf(vc), __expf(vd))),
                              h2u(__floats2half2_rn(__expf(-vc), __expf(-vd))))
                 : make_uint2(0u, 0u);
    }

    for (int kp = 0; kp < NPAIR; kp++) {
        uint2* buf = sh[kp & 1];
        buf[si0] = v0;
        if (has1) buf[si1] = v1;

        // issue next pair's loads early
        if (kp + 1 < NPAIR) {
            int ka = 2 * (kp + 1), kb = ka + 1;
            const float* __restrict__ pa = inb + (size_t)ka * NP;
            fa0 = ok0 ? __ldg(pa + off0) : 0.f;
            fa1 = (has1 && ok1) ? __ldg(pa + off1) : 0.f;
            if (kb < KC) {
                const float* __restrict__ pb = inb + (size_t)kb * NP;
                fb0 = ok0 ? __ldg(pb + off0) : 0.f;
                fb1 = (has1 && ok1) ? __ldg(pb + off1) : 0.f;
            } else { fb0 = 0.f; fb1 = 0.f; }
        }
        __syncthreads();

        uint2 ctu = buf[c00 + 3 * S1STR + 3];
        __half2 ctE = u2h(ctu.x), ctR = u2h(ctu.y);

        __half2 eh[28];
        __half2 es0 = u2h(0u), es1 = u2h(0u), es2 = u2h(0u), es3 = u2h(0u);
        #pragma unroll
        for (int r = 0; r < 4; r++) {
            const uint2* __restrict__ rp = buf + rbo[r];
            #pragma unroll
            for (int c = 0; c < 7; c++) {
                uint2 q = rp[c];
                __half2 qE = u2h(q.x), qR = u2h(q.y);
                __half2 e2 = __hmax2(__hmul2(ctE, qR), __hmul2(qE, ctR));
                eh[7 * r + c] = e2;
                if (r == 0)      es0 = __hadd2(es0, e2);
                else if (r == 1) es1 = __hadd2(es1, e2);
                else if (r == 2) es2 = __hadd2(es2, e2);
                else             es3 = __hadd2(es3, e2);
            }
        }
        __half2 es = __hadd2(__hadd2(es0, es1), __hadd2(es2, es3));
        es = __hadd2(es, u2h(__shfl_xor_sync(0xffffffffu, h2u(es), 1)));
        float eA = __half2float(__low2half(es));
        float eB = __half2float(__high2half(es));
        float sa = __fdividef(scp[2 * kp], eA);
        float sb = __fdividef(scp[2 * kp + 1], eB);
        __half2 s2 = __floats2half2_rn(sa, sb);
        #pragma unroll
        for (int j = 0; j < 28; j++) Ah[j] = __hfma2(s2, eh[j], Ah[j]);

        if (((kp & 7) == 7) || (kp == NPAIR - 1)) {  // bounded half accumulation
            #pragma unroll
            for (int j = 0; j < 28; j++) {
                float2 v = __half22float2(Ah[j]);
                A[j] += v.x + v.y;
                Ah[j] = u2h(0u);
            }
        }

        // exp for next pair (hidden under other warps' window work)
        if (kp + 1 < NPAIR) {
            float va = fa0 * m0, vb = fb0 * m0;
            v0 = ok0 ? make_uint2(h2u(__floats2half2_rn(__expf(va), __expf(vb))),
                                  h2u(__floats2half2_rn(__expf(-va), __expf(-vb))))
                     : make_uint2(0u, 0u);
            float vc = fa1 * m1, vd = fb1 * m1;
            v1 = ok1 ? make_uint2(h2u(__floats2half2_rn(__expf(vc), __expf(vd))),
                                  h2u(__floats2half2_rn(__expf(-vc), __expf(-vd))))
                     : make_uint2(0u, 0u);
        }
    }

    int gp = b * NP + (y0 + ty) * NN + (x0 + tx);
    if (h == 0) {
        #pragma unroll
        for (int j = 0; j < 28; j++) g_A[(size_t)j * TOT + gp] = A[j];      // w = j
    } else {
        #pragma unroll
        for (int j = 7; j < 28; j++) g_A[(size_t)(j + 21) * TOT + gp] = A[j]; // w = j+21
    }
}

// ---------------------------------------------------------------
// stage 2 (tiled + 4-way w-split): out[b,q,c] = sum_w A[p,w]*x2[b,c,p]
// ---------------------------------------------------------------
__global__ void __launch_bounds__(512)
stage2_kernel(const float* __restrict__ x2,
              const int*   __restrict__ mask,
              float*       __restrict__ out) {
    __shared__ float x2s[HPX * CPAD];   // ~34.5 KB
    __shared__ int   msks[HPX];

    int t  = threadIdx.x;
    int b  = blockIdx.z;
    int y0 = blockIdx.y * T2H;
    int x0 = blockIdx.x * T2W;
    const float* __restrict__ x2b = x2 + (size_t)b * CC * NP;

    if (t < HPX) {
        int hy = t / HW2, hx = t - hy * HW2;
        int gy = y0 + hy - 3, gx = x0 + hx - 3;
        bool ok = ((unsigned)gy < NN) && ((unsigned)gx < NN);
        int pl = ok ? (gy * NN + gx) : 0;
        int mv = ok ? mask[b * NP + pl] : 0;
        msks[t] = mv;
        #pragma unroll
        for (int c = 0; c < CC; c++)
            x2s[t * CPAD + c] = mv ? x2b[(size_t)c * NP + pl] : 0.0f;
        #pragma unroll
        for (int c = CC; c < CPAD; c++)
            x2s[t * CPAD + c] = 0.0f;
    }
    __syncthreads();

    int lane = t & 31;
    int wid  = t >> 5;
    int wg   = lane >> 3;
    int q    = wid * 8 + (lane & 7);
    int tx = q & 15, ty = q >> 4;
    int qy = y0 + ty, qx = x0 + tx;
    int spb = b * NP;

    float acc[CC];
    #pragma unroll
    for (int c = 0; c < CC; c++) acc[c] = 0.0f;

    int wbeg = wg * 13;
    int wend = (wbeg + 13 < WW) ? (wbeg + 13) : WW;

    for (int w = wbeg; w < wend; w++) {
        int di = (w * 37) >> 8;
        int dj = w - 7 * di;
        int hy = ty + 6 - di;
        int hx = tx + 6 - dj;
        int hh = hy * HW2 + hx;
        int mv = msks[hh];
        int gy = qy + 3 - di, gx = qx + 3 - dj;
        int pl = mv ? (gy * NN + gx) : 0;
        float a0 = g_A[(size_t)w * TOT + spb + pl];
        float a  = mv ? a0 : 0.0f;
        const float4* __restrict__ xv4 = (const float4*)(x2s + hh * CPAD);
        #pragma unroll
        for (int j = 0; j < 5; j++) {
            float4 xv = xv4[j];
            acc[4 * j + 0] = fmaf(a, xv.x, acc[4 * j + 0]);
            acc[4 * j + 1] = fmaf(a, xv.y, acc[4 * j + 1]);
            acc[4 * j + 2] = fmaf(a, xv.z, acc[4 * j + 2]);
            acc[4 * j + 3] = fmaf(a, xv.w, acc[4 * j + 3]);
        }
        acc[20] = fmaf(a, x2s[hh * CPAD + 20], acc[20]);
    }

    #pragma unroll
    for (int c = 0; c < CC; c++)
        acc[c] += __shfl_xor_sync(0xffffffffu, acc[c], 8);
    #pragma unroll
    for (int c = 0; c < CC; c++)
        acc[c] += __shfl_xor_sync(0xffffffffu, acc[c], 16);

    if (wg == 0) {
        float* o = out + (size_t)(spb + qy * NN + qx) * CC;
        #pragma unroll
        for (int c = 0; c < CC; c++) o[c] = acc[c];
    }
}

// ---------------------------------------------------------------
extern "C" void kernel_launch(void* const* d_in, const int* in_sizes, int n_in,
                              void* d_out, int out_size) {
    const float* integ = (const float*)d_in[0];   // [B,K,N,N]
    const float* x2    = (const float*)d_in[1];   // [B,C,N*N]
    const int*   msk   = (const int*)  d_in[2];   // [B,N,N]
    const float* cp    = (const float*)d_in[3];   // [K]
    float* out = (float*)d_out;                   // [B, N*N, C]

    dim3 g1(NN / S1W, NN / S1H, BN);              // (8,16,2) = 256 CTAs x 256 thr
    stage1_kernel<<<g1, 256>>>(integ, msk, cp);

    dim3 g2(NN / T2W, NN / T2H, BN);              // (8,16,2) = 256 CTAs x 512 thr
    stage2_kernel<<<g2, 512>>>(x2, msk, out);
}

// round 11
// speedup vs baseline: 1.0932x; 1.0932x over previous
#include <cuda_runtime.h>
#include <cuda_fp16.h>
#include <cstdint>

#define BN   2
#define NN   128
#define NP   (NN*NN)          // 16384
#define TOT  (BN*NP)          // 32768
#define KC   131
#define CC   21
#define WW   49
#define NCH  4                // k-chunks (wave balance: 1024 CTAs)

// stage1 tile: 16x8 outputs, 22x14 halo, padded row stride 48 (bank-safe)
#define S1W   16
#define S1H   8
#define S1HW  22
#define S1HH  14
#define S1PX  (S1HW*S1HH)     // 308 logical slots
#define S1STR 48              // padded stride (words)
#define S1BUF (S1STR*S1HH)    // 672 entries per buffer

// stage2 tile
#define T2W  16
#define T2H  8
#define HW2  22
#define HPX  (HW2*14)         // 308
#define CPAD 28               // conflict-free float4 LDS

// ---- scratch (static device globals; no runtime allocation) ----
__device__ float g_A[(size_t)NCH*WW*TOT];          // ~25.7MB

__device__ __forceinline__ unsigned h2u(__half2 v) { return *reinterpret_cast<unsigned*>(&v); }
__device__ __forceinline__ __half2 u2h(unsigned v) { return *reinterpret_cast<__half2*>(&v); }

// ncu-steering no-op (places stage1 at profiled launch slot #6)
__global__ void noop_kernel() {}

// ---------------------------------------------------------------
// stage 1 (tiled, fused exp, bank-safe): per pixel, per k:
//    A[w] += cp[k] * e_w / sum_w e_w ,  e_w = max(Ep*Rq, Eq*Rp)
//    halo loaded as raw float, masked, exp'ed into smem as
//    half2(exp(x), exp(-x)); exp for k+1 after window compute.
//    Accumulate in half2 (HFMA2), flush to float every 8 channels.
// ---------------------------------------------------------------
__global__ void __launch_bounds__(128, 4)
stage1_kernel(const float* __restrict__ integ,
              const int*   __restrict__ mask,
              const float* __restrict__ cp) {
    __shared__ __half2 sh[2][S1BUF];
    __shared__ float   scp[KC];

    int t = threadIdx.x;
    for (int k = t; k < KC; k += 128) scp[k] = cp[k];

    int b     = blockIdx.z & 1;
    int chunk = blockIdx.z >> 1;
    int x0 = blockIdx.x * S1W;
    int y0 = blockIdx.y * S1H;
    int k0 = (chunk * KC) / NCH;
    int k1 = ((chunk + 1) * KC) / NCH;

    int tx = t & 15, ty = t >> 4;

    const float* __restrict__ inb = integ + (size_t)b * KC * NP;
    const int*   __restrict__ mkb = mask  + (size_t)b * NP;
    const __half2 zero = __float2half2_rn(0.0f);

    // this thread's 3 halo fill slots (fixed across k)
    int off0, off1, off2;
    int si0, si1, si2;
    bool ok0, ok1, ok2, has2;
    float m0 = 0.f, m1 = 0.f, m2 = 0.f;
    {
        int h0 = t, h1 = t + 128, h2 = t + 256;
        int hy0 = h0 / S1HW, hx0 = h0 - hy0 * S1HW;
        int hy1 = h1 / S1HW, hx1 = h1 - hy1 * S1HW;
        int hy2 = h2 / S1HW, hx2 = h2 - hy2 * S1HW;
        si0 = hy0 * S1STR + hx0;
        si1 = hy1 * S1STR + hx1;
        si2 = hy2 * S1STR + hx2;
        int gy0 = y0 + hy0 - 3, gx0 = x0 + hx0 - 3;
        int gy1 = y0 + hy1 - 3, gx1 = x0 + hx1 - 3;
        int gy2 = y0 + hy2 - 3, gx2 = x0 + hx2 - 3;
        ok0 = ((unsigned)gy0 < NN) && ((unsigned)gx0 < NN);
        ok1 = ((unsigned)gy1 < NN) && ((unsigned)gx1 < NN);
        has2 = (h2 < S1PX);
        ok2 = has2 && ((unsigned)gy2 < NN) && ((unsigned)gx2 < NN);
        off0 = ok0 ? (gy0 * NN + gx0) : 0;
        off1 = ok1 ? (gy1 * NN + gx1) : 0;
        off2 = ok2 ? (gy2 * NN + gx2) : 0;
        if (ok0) m0 = (float)mkb[off0];
        if (ok1) m1 = (float)mkb[off1];
        if (ok2) m2 = (float)mkb[off2];
    }

    float   A[50];
    __half2 Ah[25];
    #pragma unroll
    for (int w = 0; w < 50; w++) A[w] = 0.0f;
    #pragma unroll
    for (int j = 0; j < 25; j++) Ah[j] = zero;

    // prefetch + exp for k0
    __half2 e0, e1, e2;
    {
        const float* __restrict__ ink = inb + (size_t)k0 * NP;
        float f0 = ok0 ? __ldg(ink + off0) : 0.0f;
        float f1 = ok1 ? __ldg(ink + off1) : 0.0f;
        float f2 = ok2 ? __ldg(ink + off2) : 0.0f;
        float v0 = f0 * m0, v1 = f1 * m1, v2 = f2 * m2;
        e0 = ok0 ? __floats2half2_rn(__expf(v0), __expf(-v0)) : zero;
        e1 = ok1 ? __floats2half2_rn(__expf(v1), __expf(-v1)) : zero;
        e2 = ok2 ? __floats2half2_rn(__expf(v2), __expf(-v2)) : zero;
    }

    for (int k = k0; k < k1; k++) {
        __half2* buf = sh[k & 1];
        buf[si0] = e0;
        buf[si1] = e1;
        if (has2) buf[si2] = e2;

        // issue next-k loads early
        float f0 = 0.f, f1 = 0.f, f2 = 0.f;
        if (k + 1 < k1) {
            const float* __restrict__ inn = inb + (size_t)(k + 1) * NP;
            f0 = ok0 ? __ldg(inn + off0) : 0.0f;
            f1 = ok1 ? __ldg(inn + off1) : 0.0f;
            f2 = ok2 ? __ldg(inn + off2) : 0.0f;
        }
        __syncthreads();

        const __half2* __restrict__ c00 = buf + ty * S1STR + tx;
        __half2 ct   = c00[3 * S1STR + 3];
        __half2 ctEE = __low2half2(ct);    // (Ep,Ep)
        __half2 ctRR = __high2half2(ct);   // (Rp,Rp)

        __half2 eh[25];
        __half2 esa = zero, esb = zero, esc = zero, esd = zero;
        #pragma unroll
        for (int pr = 0; pr < 24; pr++) {
            const int wa = 2 * pr, wb = wa + 1;
            __half2 qa = c00[(wa / 7) * S1STR + (wa % 7)];
            __half2 qb = c00[(wb / 7) * S1STR + (wb % 7)];
            __half2 EE = __lows2half2(qa, qb);
            __half2 RR = __highs2half2(qa, qb);
            __half2 ew = __hmax2(__hmul2(ctEE, RR), __hmul2(EE, ctRR));
            eh[pr] = ew;
            if ((pr & 3) == 0)      esa = __hadd2(esa, ew);
            else if ((pr & 3) == 1) esb = __hadd2(esb, ew);
            else if ((pr & 3) == 2) esc = __hadd2(esc, ew);
            else                    esd = __hadd2(esd, ew);
        }
        {   // singleton w=48 paired with zero (high lane of ew is 0)
            __half2 qa = c00[6 * S1STR + 6];
            __half2 EE = __lows2half2(qa, zero);
            __half2 RR = __highs2half2(qa, zero);
            __half2 ew = __hmax2(__hmul2(ctEE, RR), __hmul2(EE, ctRR));
            eh[24] = ew;
            esa = __hadd2(esa, ew);
        }
        __half2 es2 = __hadd2(__hadd2(esa, esb), __hadd2(esc, esd));
        float esum = __half2float(__hadd(__low2half(es2), __high2half(es2)));
        float s = __fdividef(scp[k], esum);
        __half2 s2 = __float2half2_rn(s);
        #pragma unroll
        for (int pr = 0; pr < 25; pr++)
            Ah[pr] = __hfma2(s2, eh[pr], Ah[pr]);

        if ((((k - k0) & 7) == 7) || (k == k1 - 1)) {   // bounded half accumulation
            #pragma unroll
            for (int pr = 0; pr < 25; pr++) {
                float2 v = __half22float2(Ah[pr]);
                A[2 * pr]     += v.x;
                A[2 * pr + 1] += v.y;
                Ah[pr] = zero;
            }
        }

        // exp for k+1 (hidden behind other warps' window work)
        if (k + 1 < k1) {
            float v0 = f0 * m0, v1 = f1 * m1, v2 = f2 * m2;
            e0 = ok0 ? __floats2half2_rn(__expf(v0), __expf(-v0)) : zero;
            e1 = ok1 ? __floats2half2_rn(__expf(v1), __expf(-v1)) : zero;
            e2 = ok2 ? __floats2half2_rn(__expf(v2), __expf(-v2)) : zero;
        }
    }

    int gp = b * NP + (y0 + ty) * NN + (x0 + tx);
    size_t baseA = (size_t)chunk * WW * TOT + gp;
    #pragma unroll
    for (int w = 0; w < WW; w++) g_A[baseA + (size_t)w * TOT] = A[w];
}

// ---------------------------------------------------------------
// stage 2 (tiled + 4-way w-split): out[b,q,c] = sum_w A[p,w]*x2[b,c,p]
// ---------------------------------------------------------------
__global__ void __launch_bounds__(512)
stage2_kernel(const float* __restrict__ x2,
              const int*   __restrict__ mask,
              float*       __restrict__ out) {
    __shared__ float x2s[HPX * CPAD];   // ~34.5 KB
    __shared__ int   msks[HPX];

    int t  = threadIdx.x;
    int b  = blockIdx.z;
    int y0 = blockIdx.y * T2H;
    int x0 = blockIdx.x * T2W;
    const float* __restrict__ x2b = x2 + (size_t)b * CC * NP;

    if (t < HPX) {
        int hy = t / HW2, hx = t - hy * HW2;
        int gy = y0 + hy - 3, gx = x0 + hx - 3;
        bool ok = ((unsigned)gy < NN) && ((unsigned)gx < NN);
        int pl = ok ? (gy * NN + gx) : 0;
        int mv = ok ? mask[b * NP + pl] : 0;
        msks[t] = mv;
        #pragma unroll
        for (int c = 0; c < CC; c++)
            x2s[t * CPAD + c] = mv ? x2b[(size_t)c * NP + pl] : 0.0f;
        #pragma unroll
        for (int c = CC; c < CPAD; c++)
            x2s[t * CPAD + c] = 0.0f;
    }
    __syncthreads();

    int lane = t & 31;
    int wid  = t >> 5;
    int wg   = lane >> 3;
    int q    = wid * 8 + (lane & 7);
    int tx = q & 15, ty = q >> 4;
    int qy = y0 + ty, qx = x0 + tx;
    int spb = b * NP;

    float acc[CC];
    #pragma unroll
    for (int c = 0; c < CC; c++) acc[c] = 0.0f;

    int wbeg = wg * 13;
    int wend = (wbeg + 13 < WW) ? (wbeg + 13) : WW;

    for (int w = wbeg; w < wend; w++) {
        int di = (w * 37) >> 8;      // w/7 for w in [0,48]
        int dj = w - 7 * di;
        int hy = ty + 6 - di;
        int hx = tx + 6 - dj;
        int hh = hy * HW2 + hx;
        int mv = msks[hh];
        int gy = qy + 3 - di, gx = qx + 3 - dj;
        int pl = mv ? (gy * NN + gx) : 0;
        size_t ai = (size_t)w * TOT + spb + pl;
        float a0 = g_A[ai];
        float a1 = g_A[(size_t)1 * WW * TOT + ai];
        float a2 = g_A[(size_t)2 * WW * TOT + ai];
        float a3 = g_A[(size_t)3 * WW * TOT + ai];
        float a  = mv ? ((a0 + a1) + (a2 + a3)) : 0.0f;
        const float4* __restrict__ xv4 = (const float4*)(x2s + hh * CPAD);
        #pragma unroll
        for (int j = 0; j < 5; j++) {
            float4 xv = xv4[j];
            acc[4 * j + 0] = fmaf(a, xv.x, acc[4 * j + 0]);
            acc[4 * j + 1] = fmaf(a, xv.y, acc[4 * j + 1]);
            acc[4 * j + 2] = fmaf(a, xv.z, acc[4 * j + 2]);
            acc[4 * j + 3] = fmaf(a, xv.w, acc[4 * j + 3]);
        }
        acc[20] = fmaf(a, x2s[hh * CPAD + 20], acc[20]);
    }

    #pragma unroll
    for (int c = 0; c < CC; c++)
        acc[c] += __shfl_xor_sync(0xffffffffu, acc[c], 8);
    #pragma unroll
    for (int c = 0; c < CC; c++)
        acc[c] += __shfl_xor_sync(0xffffffffu, acc[c], 16);

    if (wg == 0) {
        float* o = out + (size_t)(spb + qy * NN + qx) * CC;
        #pragma unroll
        for (int c = 0; c < CC; c++) o[c] = acc[c];
    }
}

// ---------------------------------------------------------------
extern "C" void kernel_launch(void* const* d_in, const int* in_sizes, int n_in,
                              void* d_out, int out_size) {
    const float* integ = (const float*)d_in[0];   // [B,K,N,N]
    const float* x2    = (const float*)d_in[1];   // [B,C,N*N]
    const int*   msk   = (const int*)  d_in[2];   // [B,N,N]
    const float* cp    = (const float*)d_in[3];   // [K]
    float* out = (float*)d_out;                   // [B, N*N, C]

    // launch order chosen so ncu (-s 5 -c 1) captures stage1_kernel
    noop_kernel<<<1, 1>>>();

    dim3 g1(NN / S1W, NN / S1H, BN * NCH);        // (8,16,8) = 1024 CTAs
    stage1_kernel<<<g1, 128>>>(integ, msk, cp);

    dim3 g2(NN / T2W, NN / T2H, BN);              // (8,16,2) = 256 CTAs
    stage2_kernel<<<g2, 512>>>(x2, msk, out);

    noop_kernel<<<1, 1>>>();
}

// round 13
// speedup vs baseline: 1.2101x; 1.1070x over previous
#include <cuda_runtime.h>
#include <cuda_fp16.h>
#include <cstdint>

#define BN   2
#define NN   128
#define NP   (NN*NN)          // 16384
#define TOT  (BN*NP)          // 32768
#define KC   131
#define CC   21
#define WW   49
#define NCH  4                // k-chunks
#define NPAIR 66              // 65 real channel pairs + phantom padding

// stage1 tile: 16x8 outputs, 22x14 halo, row stride 24 uint2 (=48 words)
#define S1W   16
#define S1H   8
#define S1HW  22
#define S1HH  14
#define S1PX  (S1HW*S1HH)     // 308 logical slots
#define S1STR 24              // padded stride in uint2 units
#define S1BUF (S1STR*S1HH)    // 336 uint2 per buffer

// stage2 tile
#define T2W  16
#define T2H  8
#define HW2  22
#define HPX  (HW2*14)         // 308
#define CPAD 28               // conflict-free float4 LDS

// ---- scratch (static device globals; no runtime allocation) ----
__device__ float g_A[(size_t)NCH*WW*TOT];          // ~25.7MB

__device__ __forceinline__ unsigned h2u(__half2 v) { return *reinterpret_cast<unsigned*>(&v); }
__device__ __forceinline__ __half2 u2h(unsigned v) { return *reinterpret_cast<__half2*>(&v); }

// ---------------------------------------------------------------
// stage 1: channel-paired window softmax accumulate.
//   smem per pixel: uint2 = (half2(E_k,E_k1), half2(R_k,R_k1))
//   per tap: 1 LDS.64 + 2 HMUL2 + 1 HMAX2 + 1 HADD2 + 1 HFMA2
//   serving TWO channels. 1 pixel/thread, no lane split, no shfl.
//   Per-lane esums stay separate (lane = channel parity).
//   Ah (half2) flushed to float A every 8 pairs.
// ---------------------------------------------------------------
__global__ void __launch_bounds__(128, 3)
stage1_kernel(const float* __restrict__ integ,
              const int*   __restrict__ mask,
              const float* __restrict__ cp) {
    __shared__ uint2 sh[2][S1BUF];
    __shared__ float scp[2 * NPAIR];

    int t = threadIdx.x;
    // strided fill: covers ALL 132 slots with 128 threads (fixes R12 bug)
    for (int k = t; k < 2 * NPAIR; k += 128)
        scp[k] = (k < KC) ? cp[k] : 0.0f;

    int b     = blockIdx.z & 1;
    int chunk = blockIdx.z >> 1;
    int x0 = blockIdx.x * S1W;
    int y0 = blockIdx.y * S1H;
    int kp0 = (chunk * NPAIR) / NCH;               // pair range of this chunk
    int kp1 = ((chunk + 1) * NPAIR) / NCH;

    int tx = t & 15, ty = t >> 4;

    const float* __restrict__ inb = integ + (size_t)b * KC * NP;
    const int*   __restrict__ mkb = mask  + (size_t)b * NP;
    const __half2 zero = __float2half2_rn(0.0f);
    const uint2   zz   = make_uint2(0u, 0u);

    // this thread's 3 halo fill slots (fixed across k)
    int off0, off1, off2;
    int si0, si1, si2;
    bool ok0, ok1, ok2, has2;
    float m0 = 0.f, m1 = 0.f, m2 = 0.f;
    {
        int h0 = t, h1 = t + 128, h2 = t + 256;
        int hy0 = h0 / S1HW, hx0 = h0 - hy0 * S1HW;
        int hy1 = h1 / S1HW, hx1 = h1 - hy1 * S1HW;
        int hy2 = h2 / S1HW, hx2 = h2 - hy2 * S1HW;
        si0 = hy0 * S1STR + hx0;
        si1 = hy1 * S1STR + hx1;
        si2 = hy2 * S1STR + hx2;
        int gy0 = y0 + hy0 - 3, gx0 = x0 + hx0 - 3;
        int gy1 = y0 + hy1 - 3, gx1 = x0 + hx1 - 3;
        int gy2 = y0 + hy2 - 3, gx2 = x0 + hx2 - 3;
        ok0 = ((unsigned)gy0 < NN) && ((unsigned)gx0 < NN);
        ok1 = ((unsigned)gy1 < NN) && ((unsigned)gx1 < NN);
        has2 = (h2 < S1PX);
        ok2 = has2 && ((unsigned)gy2 < NN) && ((unsigned)gx2 < NN);
        off0 = ok0 ? (gy0 * NN + gx0) : 0;
        off1 = ok1 ? (gy1 * NN + gx1) : 0;
        off2 = ok2 ? (gy2 * NN + gx2) : 0;
        if (ok0) m0 = (float)mkb[off0];
        if (ok1) m1 = (float)mkb[off1];
        if (ok2) m2 = (float)mkb[off2];
    }

    float   A[WW];
    __half2 Ah[WW];
    #pragma unroll
    for (int w = 0; w < WW; w++) { A[w] = 0.0f; Ah[w] = zero; }

    // prefetch + exp for pair kp0 (channels 2kp0, 2kp0+1)
    uint2 v0, v1, v2;
    {
        int ka = 2 * kp0, kb = ka + 1;
        const float* __restrict__ pa = inb + (size_t)ka * NP;
        const float* __restrict__ pb = inb + (size_t)kb * NP;
        bool bok = (kb < KC);
        float a0 = ok0 ? __ldg(pa + off0) : 0.f;
        float a1 = ok1 ? __ldg(pa + off1) : 0.f;
        float a2 = ok2 ? __ldg(pa + off2) : 0.f;
        float b0 = (ok0 && bok) ? __ldg(pb + off0) : 0.f;
        float b1 = (ok1 && bok) ? __ldg(pb + off1) : 0.f;
        float b2 = (ok2 && bok) ? __ldg(pb + off2) : 0.f;
        float xa0 = a0 * m0, xb0 = b0 * m0;
        float xa1 = a1 * m1, xb1 = b1 * m1;
        float xa2 = a2 * m2, xb2 = b2 * m2;
        v0 = ok0 ? make_uint2(h2u(__floats2half2_rn(__expf(xa0), __expf(xb0))),
                              h2u(__floats2half2_rn(__expf(-xa0), __expf(-xb0)))) : zz;
        v1 = ok1 ? make_uint2(h2u(__floats2half2_rn(__expf(xa1), __expf(xb1))),
                              h2u(__floats2half2_rn(__expf(-xa1), __expf(-xb1)))) : zz;
        v2 = ok2 ? make_uint2(h2u(__floats2half2_rn(__expf(xa2), __expf(xb2))),
                              h2u(__floats2half2_rn(__expf(-xa2), __expf(-xb2)))) : zz;
    }

    for (int kp = kp0; kp < kp1; kp++) {
        uint2* buf = sh[kp & 1];
        buf[si0] = v0;
        buf[si1] = v1;
        if (has2) buf[si2] = v2;

        // issue next pair's loads early (consumed after window compute)
        float a0 = 0.f, a1 = 0.f, a2 = 0.f, b0 = 0.f, b1 = 0.f, b2 = 0.f;
        if (kp + 1 < kp1) {
            int ka = 2 * (kp + 1), kb = ka + 1;
            const float* __restrict__ pa = inb + (size_t)ka * NP;
            a0 = ok0 ? __ldg(pa + off0) : 0.f;
            a1 = ok1 ? __ldg(pa + off1) : 0.f;
            a2 = ok2 ? __ldg(pa + off2) : 0.f;
            if (kb < KC) {
                const float* __restrict__ pb = inb + (size_t)kb * NP;
                b0 = ok0 ? __ldg(pb + off0) : 0.f;
                b1 = ok1 ? __ldg(pb + off1) : 0.f;
                b2 = ok2 ? __ldg(pb + off2) : 0.f;
            }
        }
        __syncthreads();

        const uint2* __restrict__ c00 = buf + ty * S1STR + tx;
        uint2 ctu = c00[3 * S1STR + 3];
        __half2 ctE = u2h(ctu.x);          // (E_ka, E_kb) of center
        __half2 ctR = u2h(ctu.y);          // (R_ka, R_kb)

        __half2 eh[WW];
        __half2 esa = zero, esb = zero, esc = zero, esd = zero;
        #pragma unroll
        for (int r = 0; r < 7; r++) {
            const uint2* __restrict__ rp = c00 + r * S1STR;
            #pragma unroll
            for (int c = 0; c < 7; c++) {
                uint2 q = rp[c];
                __half2 e2 = __hmax2(__hmul2(ctE, u2h(q.y)),
                                     __hmul2(u2h(q.x), ctR));
                eh[7 * r + c] = e2;
                int s = (7 * r + c) & 3;
                if (s == 0)      esa = __hadd2(esa, e2);
                else if (s == 1) esb = __hadd2(esb, e2);
                else if (s == 2) esc = __hadd2(esc, e2);
                else             esd = __hadd2(esd, e2);
            }
        }
        __half2 es = __hadd2(__hadd2(esa, esb), __hadd2(esc, esd));
        float eA = __half2float(__low2half(es));
        float eB = __half2float(__high2half(es));
        float sa = __fdividef(scp[2 * kp], eA);
        float sb = __fdividef(scp[2 * kp + 1], eB);
        __half2 s2 = __floats2half2_rn(sa, sb);
        #pragma unroll
        for (int w = 0; w < WW; w++)
            Ah[w] = __hfma2(s2, eh[w], Ah[w]);

        if ((((kp - kp0) & 7) == 7) || (kp == kp1 - 1)) {  // bounded half accum
            #pragma unroll
            for (int w = 0; w < WW; w++) {
                float2 v = __half22float2(Ah[w]);
                A[w] += v.x + v.y;
                Ah[w] = zero;
            }
        }

        // exp for next pair (hidden under other warps' window work)
        if (kp + 1 < kp1) {
            float xa0 = a0 * m0, xb0 = b0 * m0;
            float xa1 = a1 * m1, xb1 = b1 * m1;
            float xa2 = a2 * m2, xb2 = b2 * m2;
            v0 = ok0 ? make_uint2(h2u(__floats2half2_rn(__expf(xa0), __expf(xb0))),
                                  h2u(__floats2half2_rn(__expf(-xa0), __expf(-xb0)))) : zz;
            v1 = ok1 ? make_uint2(h2u(__floats2half2_rn(__expf(xa1), __expf(xb1))),
                                  h2u(__floats2half2_rn(__expf(-xa1), __expf(-xb1)))) : zz;
            v2 = ok2 ? make_uint2(h2u(__floats2half2_rn(__expf(xa2), __expf(xb2))),
                                  h2u(__floats2half2_rn(__expf(-xa2), __expf(-xb2)))) : zz;
        }
    }

    int gp = b * NP + (y0 + ty) * NN + (x0 + tx);
    size_t baseA = (size_t)chunk * WW * TOT + gp;
    #pragma unroll
    for (int w = 0; w < WW; w++) g_A[baseA + (size_t)w * TOT] = A[w];
}

// ---------------------------------------------------------------
// stage 2 (tiled + 4-way w-split): out[b,q,c] = sum_w A[p,w]*x2[b,c,p]
// ---------------------------------------------------------------
__global__ void __launch_bounds__(512)
stage2_kernel(const float* __restrict__ x2,
              const int*   __restrict__ mask,
              float*       __restrict__ out) {
    __shared__ float x2s[HPX * CPAD];   // ~34.5 KB
    __shared__ int   msks[HPX];

    int t  = threadIdx.x;
    int b  = blockIdx.z;
    int y0 = blockIdx.y * T2H;
    int x0 = blockIdx.x * T2W;
    const float* __restrict__ x2b = x2 + (size_t)b * CC * NP;

    if (t < HPX) {
        int hy = t / HW2, hx = t - hy * HW2;
        int gy = y0 + hy - 3, gx = x0 + hx - 3;
        bool ok = ((unsigned)gy < NN) && ((unsigned)gx < NN);
        int pl = ok ? (gy * NN + gx) : 0;
        int mv = ok ? mask[b * NP + pl] : 0;
        msks[t] = mv;
        #pragma unroll
        for (int c = 0; c < CC; c++)
            x2s[t * CPAD + c] = mv ? x2b[(size_t)c * NP + pl] : 0.0f;
        #pragma unroll
        for (int c = CC; c < CPAD; c++)
            x2s[t * CPAD + c] = 0.0f;
    }
    __syncthreads();

    int lane = t & 31;
    int wid  = t >> 5;
    int wg   = lane >> 3;
    int q    = wid * 8 + (lane & 7);
    int tx = q & 15, ty = q >> 4;
    int qy = y0 + ty, qx = x0 + tx;
    int spb = b * NP;

    float acc[CC];
    #pragma unroll
    for (int c = 0; c < CC; c++) acc[c] = 0.0f;

    int wbeg = wg * 13;
    int wend = (wbeg + 13 < WW) ? (wbeg + 13) : WW;

    for (int w = wbeg; w < wend; w++) {
        int di = (w * 37) >> 8;      // w/7 for w in [0,48]
        int dj = w - 7 * di;
        int hy = ty + 6 - di;
        int hx = tx + 6 - dj;
        int hh = hy * HW2 + hx;
        int mv = msks[hh];
        int gy = qy + 3 - di, gx = qx + 3 - dj;
        int pl = mv ? (gy * NN + gx) : 0;
        size_t ai = (size_t)w * TOT + spb + pl;
        float a0 = g_A[ai];
        float a1 = g_A[(size_t)1 * WW * TOT + ai];
        float a2 = g_A[(size_t)2 * WW * TOT + ai];
        float a3 = g_A[(size_t)3 * WW * TOT + ai];
        float a  = mv ? ((a0 + a1) + (a2 + a3)) : 0.0f;
        const float4* __restrict__ xv4 = (const float4*)(x2s + hh * CPAD);
        #pragma unroll
        for (int j = 0; j < 5; j++) {
            float4 xv = xv4[j];
            acc[4 * j + 0] = fmaf(a, xv.x, acc[4 * j + 0]);
            acc[4 * j + 1] = fmaf(a, xv.y, acc[4 * j + 1]);
            acc[4 * j + 2] = fmaf(a, xv.z, acc[4 * j + 2]);
            acc[4 * j + 3] = fmaf(a, xv.w, acc[4 * j + 3]);
        }
        acc[20] = fmaf(a, x2s[hh * CPAD + 20], acc[20]);
    }

    #pragma unroll
    for (int c = 0; c < CC; c++)
        acc[c] += __shfl_xor_sync(0xffffffffu, acc[c], 8);
    #pragma unroll
    for (int c = 0; c < CC; c++)
        acc[c] += __shfl_xor_sync(0xffffffffu, acc[c], 16);

    if (wg == 0) {
        float* o = out + (size_t)(spb + qy * NN + qx) * CC;
        #pragma unroll
        for (int c = 0; c < CC; c++) o[c] = acc[c];
    }
}

// ---------------------------------------------------------------
extern "C" void kernel_launch(void* const* d_in, const int* in_sizes, int n_in,
                              void* d_out, int out_size) {
    const float* integ = (const float*)d_in[0];   // [B,K,N,N]
    const float* x2    = (const float*)d_in[1];   // [B,C,N*N]
    const int*   msk   = (const int*)  d_in[2];   // [B,N,N]
    const float* cp    = (const float*)d_in[3];   // [K]
    float* out = (float*)d_out;                   // [B, N*N, C]

    dim3 g1(NN / S1W, NN / S1H, BN * NCH);        // (8,16,8) = 1024 CTAs
    stage1_kernel<<<g1, 128>>>(integ, msk, cp);

    dim3 g2(NN / T2W, NN / T2H, BN);              // (8,16,2) = 256 CTAs
    stage2_kernel<<<g2, 512>>>(x2, msk, out);
}